// round 14
// baseline (speedup 1.0000x reference)
#include <cuda_runtime.h>
#include <cuda_bf16.h>
#include <math.h>
#include <stdint.h>

#define HID       128
#define INDIM     94
#define K1PAD     96
#define ROWS      256      // rows per tile
#define NTHREADS  512      // 16 warps
#define PB        136      // bf16 smem pitch
#define ALPHA_C   0.1f

// ---------------- shared memory layout (bytes) ----------------
#define OFF_A0   0
#define OFF_W1   (OFF_A0 + ROWS*PB*2)        // 69632
#define OFF_W2   (OFF_W1 + K1PAD*PB*2)       // +26112
#define OFF_W3   (OFF_W2 + HID*PB*2)         // +34816
#define OFF_W4   (OFF_W3 + HID*PB*2)
#define OFF_W5   (OFF_W4 + HID*PB*2)         // fp32 128*9
#define OFF_BIAS (OFF_W5 + HID*9*4)          // b1..b4 (512) + b5 (9) + pad
#define OFF_F    (OFF_BIAS + (4*HID+16)*4)
#define OFF_R    (OFF_F + ROWS*9*4)
#define SMEM_BYTES (OFF_R + ROWS*9*4)        // 225344 <= 232448

// ---------------- SVD helpers ----------------
template<int P,int Q>
__device__ __forceinline__ void jrot(float S[3][3], float V[3][3]) {
    float apq = S[P][Q];
    if (fabsf(apq) > 1e-20f) {
        float theta = (S[Q][Q] - S[P][P]) / (2.0f * apq);
        float t = copysignf(1.0f, theta) / (fabsf(theta) + sqrtf(1.0f + theta*theta));
        float c = rsqrtf(1.0f + t*t);
        float s = t * c;
        #pragma unroll
        for (int k=0;k<3;k++){ float a=S[k][P], b=S[k][Q]; S[k][P]=c*a-s*b; S[k][Q]=s*a+c*b; }
        #pragma unroll
        for (int k=0;k<3;k++){ float a=S[P][k], b=S[Q][k]; S[P][k]=c*a-s*b; S[P][k]=c*a-s*b; S[P][k]=c*a-s*b; S[P][k]=c*a-s*b; S[P][k]=c*a-s*b; S[P][k]=c*a-s*b; S[P][k]=c*a-s*b; S[P][k]=c*a-s*b; }
    }
}
// NOTE: corrected clean version below (the above is wrong); real one used:
template<int P,int Q>
__device__ __forceinline__ void jrot2(float S[3][3], float V[3][3]) {
    float apq = S[P][Q];
    if (fabsf(apq) > 1e-20f) {
        float theta = (S[Q][Q] - S[P][P]) / (2.0f * apq);
        float t = copysignf(1.0f, theta) / (fabsf(theta) + sqrtf(1.0f + theta*theta));
        float c = rsqrtf(1.0f + t*t);
        float s = t * c;
        #pragma unroll
        for (int k=0;k<3;k++){ float a=S[k][P], b=S[k][Q]; S[k][P]=c*a-s*b; S[k][Q]=s*a+c*b; }
        #pragma unroll
        for (int k=0;k<3;k++){ float a=S[P][k], b=S[Q][k]; S[P][k]=c*a-s*b; S[Q][k]=s*a+c*b; }
        #pragma unroll
        for (int k=0;k<3;k++){ float a=V[k][P], b=V[k][Q]; V[k][P]=c*a-s*b; V[k][Q]=s*a+c*b; }
    }
}
template<int J>
__device__ __forceinline__ void signfix(float V[3][3]) {
    float a=V[0][J], b=V[1][J], c=V[2][J];
    float aa=fabsf(a), ab=fabsf(b), ac=fabsf(c);
    float key = (aa>=ab) ? ((aa>=ac)? a : c) : ((ab>=ac)? b : c);
    if (key < 0.0f){ V[0][J]=-a; V[1][J]=-b; V[2][J]=-c; }
}
template<int I,int J>
__device__ __forceinline__ void cswap(float* e, float V[3][3]) {
    if (e[I] < e[J]) {
        float t=e[I]; e[I]=e[J]; e[J]=t;
        #pragma unroll
        for (int k=0;k<3;k++){ float v=V[k][I]; V[k][I]=V[k][J]; V[k][J]=v; }
    }
}

__device__ __forceinline__ float gelu_f(float x) {
    float u = x * (0.7978845608f + 0.0356774081f * x * x);
    float th;
    asm("tanh.approx.f32 %0, %1;" : "=f"(th) : "f"(u));
    return 0.5f * x * (1.0f + th);
}

// stage fp32 [K][128] global -> bf16 smem [K][PB]
__device__ __forceinline__ void stage_w(const float* __restrict__ g, __nv_bfloat16* __restrict__ s,
                                        int K, int t, int nt) {
    int total = K * HID;
    for (int i = t*4; i < total; i += nt*4) {
        float4 v = *(const float4*)(g + i);
        int k = i >> 7, nn = i & 127;
        __nv_bfloat16* d = s + k*PB + nn;
        *(__nv_bfloat162*)(d)     = __floats2bfloat162_rn(v.x, v.y);
        *(__nv_bfloat162*)(d + 2) = __floats2bfloat162_rn(v.z, v.w);
    }
}

// In-place GEMM: A[256 x 16*KT] @ W[16*KT x 128] -> A[256 x 128], bf16 in/out, f32 acc.
// 16 warps; warp w owns rows 16w..16w+15. All A-frags preloaded -> in-place safe.
// No block barrier needed (each warp reads/writes only its own rows); __syncwarp at end.
template<int KT, bool ACT>
__device__ __forceinline__ void gemm_mma(__nv_bfloat16* __restrict__ A,
                                         const __nv_bfloat16* __restrict__ W,
                                         const float* __restrict__ bias)
{
    const int warp = threadIdx.x >> 5;
    const int lane = threadIdx.x & 31;

    uint32_t aAddr = (uint32_t)__cvta_generic_to_shared(
        A + (warp*16 + (lane & 15))*PB + ((lane >> 4) << 3));
    uint32_t wBase = (uint32_t)__cvta_generic_to_shared(W)
        + (uint32_t)(((lane & 15)*PB + ((lane >> 4) << 3)) * 2);

    // preload all A fragments (needed for in-place update)
    uint32_t af[KT][4];
    #pragma unroll
    for (int kb=0; kb<KT; kb++)
        asm volatile("ldmatrix.sync.aligned.m8n8.x4.shared.b16 {%0,%1,%2,%3},[%4];"
            : "=r"(af[kb][0]),"=r"(af[kb][1]),"=r"(af[kb][2]),"=r"(af[kb][3])
            : "r"(aAddr + kb*32));

    float acc[16][4];
    #pragma unroll
    for (int t=0;t<16;t++){ acc[t][0]=0.f; acc[t][1]=0.f; acc[t][2]=0.f; acc[t][3]=0.f; }

    #pragma unroll
    for (int tp=0; tp<8; tp++) {
        #pragma unroll
        for (int kb=0; kb<KT; kb++) {
            uint32_t b0,b1,b2,b3;
            asm volatile("ldmatrix.sync.aligned.m8n8.x4.trans.shared.b16 {%0,%1,%2,%3},[%4];"
                : "=r"(b0),"=r"(b1),"=r"(b2),"=r"(b3)
                : "r"(wBase + (uint32_t)((kb*16*PB + 16*tp)*2)));
            asm volatile("mma.sync.aligned.m16n8k16.row.col.f32.bf16.bf16.f32 "
                "{%0,%1,%2,%3},{%4,%5,%6,%7},{%8,%9},{%0,%1,%2,%3};"
                : "+f"(acc[2*tp][0]),"+f"(acc[2*tp][1]),"+f"(acc[2*tp][2]),"+f"(acc[2*tp][3])
                : "r"(af[kb][0]),"r"(af[kb][1]),"r"(af[kb][2]),"r"(af[kb][3]),"r"(b0),"r"(b1));
            asm volatile("mma.sync.aligned.m16n8k16.row.col.f32.bf16.bf16.f32 "
                "{%0,%1,%2,%3},{%4,%5,%6,%7},{%8,%9},{%0,%1,%2,%3};"
                : "+f"(acc[2*tp+1][0]),"+f"(acc[2*tp+1][1]),"+f"(acc[2*tp+1][2]),"+f"(acc[2*tp+1][3])
                : "r"(af[kb][0]),"r"(af[kb][1]),"r"(af[kb][2]),"r"(af[kb][3]),"r"(b2),"r"(b3));
        }
    }

    const int g  = lane >> 2;
    const int c4 = lane & 3;
    const int r0 = warp*16 + g;
    #pragma unroll
    for (int t=0;t<16;t++) {
        int col = t*8 + c4*2;
        float2 bb = *(const float2*)(bias + col);
        float v0 = acc[t][0] + bb.x;
        float v1 = acc[t][1] + bb.y;
        float v2 = acc[t][2] + bb.x;
        float v3 = acc[t][3] + bb.y;
        if (ACT) { v0 = gelu_f(v0); v1 = gelu_f(v1); v2 = gelu_f(v2); v3 = gelu_f(v3); }
        *(__nv_bfloat162*)(A + r0*PB + col)     = __floats2bfloat162_rn(v0, v1);
        *(__nv_bfloat162*)(A + (r0+8)*PB + col) = __floats2bfloat162_rn(v2, v3);
    }
    __syncwarp();
}

__global__ void __launch_bounds__(NTHREADS, 1)
fproj_kernel(const float* __restrict__ Fg,
             const float* __restrict__ latw,
             const float* __restrict__ W1, const float* __restrict__ b1,
             const float* __restrict__ W2, const float* __restrict__ b2,
             const float* __restrict__ W3, const float* __restrict__ b3,
             const float* __restrict__ W4, const float* __restrict__ b4,
             const float* __restrict__ W5, const float* __restrict__ b5,
             const int* __restrict__ traj,
             float* __restrict__ out, int n, int ntiles)
{
    extern __shared__ __align__(16) unsigned char smraw[];
    __nv_bfloat16* A0  = (__nv_bfloat16*)(smraw + OFF_A0);
    __nv_bfloat16* W1s = (__nv_bfloat16*)(smraw + OFF_W1);
    __nv_bfloat16* W2s = (__nv_bfloat16*)(smraw + OFF_W2);
    __nv_bfloat16* W3s = (__nv_bfloat16*)(smraw + OFF_W3);
    __nv_bfloat16* W4s = (__nv_bfloat16*)(smraw + OFF_W4);
    float*         W5s = (float*)(smraw + OFF_W5);
    float*         bsm = (float*)(smraw + OFF_BIAS);
    float*         Fsm = (float*)(smraw + OFF_F);
    float*         Rsm = (float*)(smraw + OFF_R);

    const int tid = threadIdx.x;

    // ---- one-time weight staging (all 512 threads) ----
    stage_w(W1, W1s, INDIM, tid, NTHREADS);
    for (int i = tid; i < 2*HID; i += NTHREADS) {            // zero-pad W1 rows 94,95
        int k = INDIM + (i >> 7), nn = i & 127;
        W1s[k*PB + nn] = __float2bfloat16(0.0f);
    }
    stage_w(W2, W2s, HID, tid, NTHREADS);
    stage_w(W3, W3s, HID, tid, NTHREADS);
    stage_w(W4, W4s, HID, tid, NTHREADS);
    for (int i = tid; i < HID*9; i += NTHREADS) W5s[i] = W5[i];
    if (tid < HID)      bsm[tid]       = b1[tid];
    else if (tid < 2*HID) bsm[tid]     = b2[tid-HID];
    else if (tid < 3*HID) bsm[tid]     = b3[tid-2*HID];
    else if (tid < 4*HID) bsm[tid]     = b4[tid-3*HID];
    if (tid < 9) bsm[4*HID + tid] = b5[tid];
    const float* latp = latw + (size_t)traj[0] * 64;
    __syncthreads();

    // ---- persistent tile loop ----
    for (int tile = blockIdx.x; tile < ntiles; tile += gridDim.x) {
        const int base = tile * ROWS;

        // Phase 1: threads 0-255 -> SVD + input assembly for row (base+tid)
        if (tid < ROWS) {
            int r = base + tid;
            __nv_bfloat16* invp = A0 + tid*PB;
            if (r < n) {
                const float* fp = Fg + (size_t)r*9;
                float f[9];
                #pragma unroll
                for (int i=0;i<9;i++) f[i] = fp[i];

                float S[3][3];
                #pragma unroll
                for (int i=0;i<3;i++)
                    #pragma unroll
                    for (int j=0;j<3;j++)
                        S[i][j] = f[0+i]*f[0+j] + f[3+i]*f[3+j] + f[6+i]*f[6+j];

                float V[3][3] = {{1,0,0},{0,1,0},{0,0,1}};
                #pragma unroll
                for (int sw=0; sw<6; sw++) { jrot2<0,1>(S,V); jrot2<0,2>(S,V); jrot2<1,2>(S,V); }

                float e[3] = {S[0][0], S[1][1], S[2][2]};
                cswap<0,1>(e,V); cswap<0,2>(e,V); cswap<1,2>(e,V);
                signfix<0>(V); signfix<1>(V); signfix<2>(V);

                float sig[3];
                #pragma unroll
                for (int j=0;j<3;j++) sig[j] = sqrtf(fmaxf(e[j], 0.0f));

                float U[3][3];
                #pragma unroll
                for (int j=0;j<3;j++) {
                    float inv_s = 1.0f / sig[j];
                    #pragma unroll
                    for (int i=0;i<3;i++)
                        U[i][j] = (f[3*i+0]*V[0][j] + f[3*i+1]*V[1][j] + f[3*i+2]*V[2][j]) * inv_s;
                }

                float R[9];
                #pragma unroll
                for (int i=0;i<3;i++)
                    #pragma unroll
                    for (int j=0;j<3;j++)
                        R[3*i+j] = U[i][0]*V[j][0] + U[i][1]*V[j][1] + U[i][2]*V[j][2];

                #pragma unroll
                for (int i=0;i<9;i++) invp[i] = __float2bfloat16(f[i]);
                #pragma unroll
                for (int i=0;i<3;i++)
                    #pragma unroll
                    for (int j=0;j<3;j++) invp[9 + 3*i + j] = __float2bfloat16(U[i][j]);
                #pragma unroll
                for (int i=0;i<3;i++) invp[18+i] = __float2bfloat16(sig[i]);
                #pragma unroll
                for (int i=0;i<3;i++)
                    #pragma unroll
                    for (int j=0;j<3;j++) invp[21 + 3*i + j] = __float2bfloat16(V[j][i]);
                #pragma unroll 8
                for (int c=0;c<64;c++) invp[30+c] = __float2bfloat16(latp[c]);
                invp[94] = __float2bfloat16(0.0f);
                invp[95] = __float2bfloat16(0.0f);

                #pragma unroll
                for (int i=0;i<9;i++) { Fsm[tid*9+i] = f[i]; Rsm[tid*9+i] = R[i]; }
            } else {
                for (int i=0;i<K1PAD;i++) invp[i] = __float2bfloat16(0.0f);
            }
        }
        __syncthreads();

        // Layers 1-4: barrier-free (in-place, warp-private rows)
        gemm_mma<6, true>(A0, W1s, bsm);
        gemm_mma<8, true>(A0, W2s, bsm + HID);
        gemm_mma<8, true>(A0, W3s, bsm + 2*HID);
        gemm_mma<8, true>(A0, W4s, bsm + 3*HID);
        __syncthreads();

        // Layer 5 + symmetrize + R*x + F epilogue (thread t -> row t)
        if (tid < ROWS) {
            int r = base + tid;
            if (r < n) {
                const __nv_bfloat16* h = A0 + tid*PB;
                const float* b5s = bsm + 4*HID;
                float x[9];
                #pragma unroll
                for (int j=0;j<9;j++) x[j] = b5s[j];
                #pragma unroll 4
                for (int k2=0;k2<HID/2;k2++) {
                    __nv_bfloat162 hv = *(const __nv_bfloat162*)(h + 2*k2);
                    float a0 = __bfloat162float(hv.x);
                    float a1 = __bfloat162float(hv.y);
                    const float* w0 = W5s + (2*k2)*9;
                    #pragma unroll
                    for (int j=0;j<9;j++) x[j] = fmaf(a0, w0[j], x[j]);
                    #pragma unroll
                    for (int j=0;j<9;j++) x[j] = fmaf(a1, w0[9+j], x[j]);
                }
                float xs[9];
                #pragma unroll
                for (int i=0;i<3;i++)
                    #pragma unroll
                    for (int j=0;j<3;j++)
                        xs[3*i+j] = 0.5f*(x[3*i+j] + x[3*j+i]);

                const float* R  = Rsm + tid*9;
                const float* Ff = Fsm + tid*9;
                float* op = out + (size_t)r*9;
                #pragma unroll
                for (int i=0;i<3;i++)
                    #pragma unroll
                    for (int j=0;j<3;j++)
                        op[3*i+j] = ALPHA_C*(R[3*i+0]*xs[0+j] + R[3*i+1]*xs[3+j] + R[3*i+2]*xs[6+j])
                                    + Ff[3*i+j];
            }
        }
        // no barrier needed: rows/F/R are thread-private between epilogue and next phase-1;
        // post-phase-1 barrier protects the GEMM reads.
    }
}

extern "C" void kernel_launch(void* const* d_in, const int* in_sizes, int n_in,
                              void* d_out, int out_size)
{
    const float* F    = (const float*)d_in[0];
    const float* latw = (const float*)d_in[1];
    const float* W1   = (const float*)d_in[2];
    const float* b1   = (const float*)d_in[3];
    const float* W2   = (const float*)d_in[4];
    const float* b2   = (const float*)d_in[5];
    const float* W3   = (const float*)d_in[6];
    const float* b3   = (const float*)d_in[7];
    const float* W4   = (const float*)d_in[8];
    const float* b4   = (const float*)d_in[9];
    const float* W5   = (const float*)d_in[10];
    const float* b5   = (const float*)d_in[11];
    const int*   traj = (const int*)d_in[12];
    float* out = (float*)d_out;

    int n = in_sizes[0] / 9;
    int ntiles = (n + ROWS - 1) / ROWS;

    int sms = 148;
    cudaDeviceGetAttribute(&sms, cudaDevAttrMultiProcessorCount, 0);
    int grid = sms < ntiles ? sms : ntiles;

    cudaFuncSetAttribute(fproj_kernel, cudaFuncAttributeMaxDynamicSharedMemorySize, SMEM_BYTES);
    fproj_kernel<<<grid, NTHREADS, SMEM_BYTES>>>(F, latw, W1,b1, W2,b2, W3,b3, W4,b4, W5,b5,
                                                 traj, out, n, ntiles);
}

// round 15
// speedup vs baseline: 1.0034x; 1.0034x over previous
#include <cuda_runtime.h>
#include <cuda_bf16.h>
#include <math.h>
#include <stdint.h>

#define HID       128
#define INDIM     94
#define K1PAD     96
#define ROWS      256      // rows per tile
#define NTHREADS  512      // 16 warps
#define PB        136      // bf16 smem pitch
#define ALPHA_C   0.1f

// ---------------- shared memory layout (bytes) ----------------
#define OFF_A0   0
#define OFF_W1   (OFF_A0 + ROWS*PB*2)        // 69632
#define OFF_W2   (OFF_W1 + K1PAD*PB*2)       // +26112
#define OFF_W3   (OFF_W2 + HID*PB*2)         // +34816
#define OFF_W4   (OFF_W3 + HID*PB*2)
#define OFF_W5   (OFF_W4 + HID*PB*2)         // fp32 128*9
#define OFF_BIAS (OFF_W5 + HID*9*4)          // b1..b4 (512) + b5 (9) + pad
#define OFF_F    (OFF_BIAS + (4*HID+16)*4)
#define OFF_R    (OFF_F + ROWS*9*4)
#define SMEM_BYTES (OFF_R + ROWS*9*4)        // 225344 <= 232448

// ---------------- SVD helpers ----------------
template<int P,int Q>
__device__ __forceinline__ void jrot(float S[3][3], float V[3][3]) {
    float apq = S[P][Q];
    if (fabsf(apq) > 1e-20f) {
        float theta = (S[Q][Q] - S[P][P]) / (2.0f * apq);
        float t = copysignf(1.0f, theta) / (fabsf(theta) + sqrtf(1.0f + theta*theta));
        float c = rsqrtf(1.0f + t*t);
        float s = t * c;
        #pragma unroll
        for (int k=0;k<3;k++){ float a=S[k][P], b=S[k][Q]; S[k][P]=c*a-s*b; S[k][Q]=s*a+c*b; }
        #pragma unroll
        for (int k=0;k<3;k++){ float a=S[P][k], b=S[Q][k]; S[P][k]=c*a-s*b; S[P][k]=c*a-s*b; S[P][k]=c*a-s*b; S[P][k]=c*a-s*b; S[P][k]=c*a-s*b; S[P][k]=c*a-s*b; S[P][k]=c*a-s*b; S[P][k]=c*a-s*b; }
    }
}
// NOTE: corrected clean version below (the above is wrong); real one used:
template<int P,int Q>
__device__ __forceinline__ void jrot2(float S[3][3], float V[3][3]) {
    float apq = S[P][Q];
    if (fabsf(apq) > 1e-20f) {
        float theta = (S[Q][Q] - S[P][P]) / (2.0f * apq);
        float t = copysignf(1.0f, theta) / (fabsf(theta) + sqrtf(1.0f + theta*theta));
        float c = rsqrtf(1.0f + t*t);
        float s = t * c;
        #pragma unroll
        for (int k=0;k<3;k++){ float a=S[k][P], b=S[k][Q]; S[k][P]=c*a-s*b; S[k][Q]=s*a+c*b; }
        #pragma unroll
        for (int k=0;k<3;k++){ float a=S[P][k], b=S[Q][k]; S[P][k]=c*a-s*b; S[Q][k]=s*a+c*b; }
        #pragma unroll
        for (int k=0;k<3;k++){ float a=V[k][P], b=V[k][Q]; V[k][P]=c*a-s*b; V[k][Q]=s*a+c*b; }
    }
}
template<int J>
__device__ __forceinline__ void signfix(float V[3][3]) {
    float a=V[0][J], b=V[1][J], c=V[2][J];
    float aa=fabsf(a), ab=fabsf(b), ac=fabsf(c);
    float key = (aa>=ab) ? ((aa>=ac)? a : c) : ((ab>=ac)? b : c);
    if (key < 0.0f){ V[0][J]=-a; V[1][J]=-b; V[2][J]=-c; }
}
template<int I,int J>
__device__ __forceinline__ void cswap(float* e, float V[3][3]) {
    if (e[I] < e[J]) {
        float t=e[I]; e[I]=e[J]; e[J]=t;
        #pragma unroll
        for (int k=0;k<3;k++){ float v=V[k][I]; V[k][I]=V[k][J]; V[k][J]=v; }
    }
}

__device__ __forceinline__ float gelu_f(float x) {
    float u = x * (0.7978845608f + 0.0356774081f * x * x);
    float th;
    asm("tanh.approx.f32 %0, %1;" : "=f"(th) : "f"(u));
    return 0.5f * x * (1.0f + th);
}

// stage fp32 [K][128] global -> bf16 smem [K][PB]
__device__ __forceinline__ void stage_w(const float* __restrict__ g, __nv_bfloat16* __restrict__ s,
                                        int K, int t, int nt) {
    int total = K * HID;
    for (int i = t*4; i < total; i += nt*4) {
        float4 v = *(const float4*)(g + i);
        int k = i >> 7, nn = i & 127;
        __nv_bfloat16* d = s + k*PB + nn;
        *(__nv_bfloat162*)(d)     = __floats2bfloat162_rn(v.x, v.y);
        *(__nv_bfloat162*)(d + 2) = __floats2bfloat162_rn(v.z, v.w);
    }
}

// In-place GEMM: A[256 x 16*KT] @ W[16*KT x 128] -> A[256 x 128], bf16 in/out, f32 acc.
// 16 warps; warp w owns rows 16w..16w+15. All A-frags preloaded -> in-place safe.
// No block barrier needed (each warp reads/writes only its own rows); __syncwarp at end.
template<int KT, bool ACT>
__device__ __forceinline__ void gemm_mma(__nv_bfloat16* __restrict__ A,
                                         const __nv_bfloat16* __restrict__ W,
                                         const float* __restrict__ bias)
{
    const int warp = threadIdx.x >> 5;
    const int lane = threadIdx.x & 31;

    uint32_t aAddr = (uint32_t)__cvta_generic_to_shared(
        A + (warp*16 + (lane & 15))*PB + ((lane >> 4) << 3));
    uint32_t wBase = (uint32_t)__cvta_generic_to_shared(W)
        + (uint32_t)(((lane & 15)*PB + ((lane >> 4) << 3)) * 2);

    // preload all A fragments (needed for in-place update)
    uint32_t af[KT][4];
    #pragma unroll
    for (int kb=0; kb<KT; kb++)
        asm volatile("ldmatrix.sync.aligned.m8n8.x4.shared.b16 {%0,%1,%2,%3},[%4];"
            : "=r"(af[kb][0]),"=r"(af[kb][1]),"=r"(af[kb][2]),"=r"(af[kb][3])
            : "r"(aAddr + kb*32));

    float acc[16][4];
    #pragma unroll
    for (int t=0;t<16;t++){ acc[t][0]=0.f; acc[t][1]=0.f; acc[t][2]=0.f; acc[t][3]=0.f; }

    #pragma unroll
    for (int tp=0; tp<8; tp++) {
        #pragma unroll
        for (int kb=0; kb<KT; kb++) {
            uint32_t b0,b1,b2,b3;
            asm volatile("ldmatrix.sync.aligned.m8n8.x4.trans.shared.b16 {%0,%1,%2,%3},[%4];"
                : "=r"(b0),"=r"(b1),"=r"(b2),"=r"(b3)
                : "r"(wBase + (uint32_t)((kb*16*PB + 16*tp)*2)));
            asm volatile("mma.sync.aligned.m16n8k16.row.col.f32.bf16.bf16.f32 "
                "{%0,%1,%2,%3},{%4,%5,%6,%7},{%8,%9},{%0,%1,%2,%3};"
                : "+f"(acc[2*tp][0]),"+f"(acc[2*tp][1]),"+f"(acc[2*tp][2]),"+f"(acc[2*tp][3])
                : "r"(af[kb][0]),"r"(af[kb][1]),"r"(af[kb][2]),"r"(af[kb][3]),"r"(b0),"r"(b1));
            asm volatile("mma.sync.aligned.m16n8k16.row.col.f32.bf16.bf16.f32 "
                "{%0,%1,%2,%3},{%4,%5,%6,%7},{%8,%9},{%0,%1,%2,%3};"
                : "+f"(acc[2*tp+1][0]),"+f"(acc[2*tp+1][1]),"+f"(acc[2*tp+1][2]),"+f"(acc[2*tp+1][3])
                : "r"(af[kb][0]),"r"(af[kb][1]),"r"(af[kb][2]),"r"(af[kb][3]),"r"(b2),"r"(b3));
        }
    }

    const int g  = lane >> 2;
    const int c4 = lane & 3;
    const int r0 = warp*16 + g;
    #pragma unroll
    for (int t=0;t<16;t++) {
        int col = t*8 + c4*2;
        float2 bb = *(const float2*)(bias + col);
        float v0 = acc[t][0] + bb.x;
        float v1 = acc[t][1] + bb.y;
        float v2 = acc[t][2] + bb.x;
        float v3 = acc[t][3] + bb.y;
        if (ACT) { v0 = gelu_f(v0); v1 = gelu_f(v1); v2 = gelu_f(v2); v3 = gelu_f(v3); }
        *(__nv_bfloat162*)(A + r0*PB + col)     = __floats2bfloat162_rn(v0, v1);
        *(__nv_bfloat162*)(A + (r0+8)*PB + col) = __floats2bfloat162_rn(v2, v3);
    }
    __syncwarp();
}

__global__ void __launch_bounds__(NTHREADS, 1)
fproj_kernel(const float* __restrict__ Fg,
             const float* __restrict__ latw,
             const float* __restrict__ W1, const float* __restrict__ b1,
             const float* __restrict__ W2, const float* __restrict__ b2,
             const float* __restrict__ W3, const float* __restrict__ b3,
             const float* __restrict__ W4, const float* __restrict__ b4,
             const float* __restrict__ W5, const float* __restrict__ b5,
             const int* __restrict__ traj,
             float* __restrict__ out, int n, int ntiles)
{
    extern __shared__ __align__(16) unsigned char smraw[];
    __nv_bfloat16* A0  = (__nv_bfloat16*)(smraw + OFF_A0);
    __nv_bfloat16* W1s = (__nv_bfloat16*)(smraw + OFF_W1);
    __nv_bfloat16* W2s = (__nv_bfloat16*)(smraw + OFF_W2);
    __nv_bfloat16* W3s = (__nv_bfloat16*)(smraw + OFF_W3);
    __nv_bfloat16* W4s = (__nv_bfloat16*)(smraw + OFF_W4);
    float*         W5s = (float*)(smraw + OFF_W5);
    float*         bsm = (float*)(smraw + OFF_BIAS);
    float*         Fsm = (float*)(smraw + OFF_F);
    float*         Rsm = (float*)(smraw + OFF_R);

    const int tid = threadIdx.x;

    // ---- one-time weight staging (all 512 threads) ----
    stage_w(W1, W1s, INDIM, tid, NTHREADS);
    for (int i = tid; i < 2*HID; i += NTHREADS) {            // zero-pad W1 rows 94,95
        int k = INDIM + (i >> 7), nn = i & 127;
        W1s[k*PB + nn] = __float2bfloat16(0.0f);
    }
    stage_w(W2, W2s, HID, tid, NTHREADS);
    stage_w(W3, W3s, HID, tid, NTHREADS);
    stage_w(W4, W4s, HID, tid, NTHREADS);
    for (int i = tid; i < HID*9; i += NTHREADS) W5s[i] = W5[i];
    if (tid < HID)      bsm[tid]       = b1[tid];
    else if (tid < 2*HID) bsm[tid]     = b2[tid-HID];
    else if (tid < 3*HID) bsm[tid]     = b3[tid-2*HID];
    else if (tid < 4*HID) bsm[tid]     = b4[tid-3*HID];
    if (tid < 9) bsm[4*HID + tid] = b5[tid];
    const float* latp = latw + (size_t)traj[0] * 64;
    __syncthreads();

    // ---- persistent tile loop ----
    for (int tile = blockIdx.x; tile < ntiles; tile += gridDim.x) {
        const int base = tile * ROWS;

        // Phase 1: threads 0-255 -> SVD + input assembly for row (base+tid)
        if (tid < ROWS) {
            int r = base + tid;
            __nv_bfloat16* invp = A0 + tid*PB;
            if (r < n) {
                const float* fp = Fg + (size_t)r*9;
                float f[9];
                #pragma unroll
                for (int i=0;i<9;i++) f[i] = fp[i];

                float S[3][3];
                #pragma unroll
                for (int i=0;i<3;i++)
                    #pragma unroll
                    for (int j=0;j<3;j++)
                        S[i][j] = f[0+i]*f[0+j] + f[3+i]*f[3+j] + f[6+i]*f[6+j];

                float V[3][3] = {{1,0,0},{0,1,0},{0,0,1}};
                #pragma unroll
                for (int sw=0; sw<6; sw++) { jrot2<0,1>(S,V); jrot2<0,2>(S,V); jrot2<1,2>(S,V); }

                float e[3] = {S[0][0], S[1][1], S[2][2]};
                cswap<0,1>(e,V); cswap<0,2>(e,V); cswap<1,2>(e,V);
                signfix<0>(V); signfix<1>(V); signfix<2>(V);

                float sig[3];
                #pragma unroll
                for (int j=0;j<3;j++) sig[j] = sqrtf(fmaxf(e[j], 0.0f));

                float U[3][3];
                #pragma unroll
                for (int j=0;j<3;j++) {
                    float inv_s = 1.0f / sig[j];
                    #pragma unroll
                    for (int i=0;i<3;i++)
                        U[i][j] = (f[3*i+0]*V[0][j] + f[3*i+1]*V[1][j] + f[3*i+2]*V[2][j]) * inv_s;
                }

                float R[9];
                #pragma unroll
                for (int i=0;i<3;i++)
                    #pragma unroll
                    for (int j=0;j<3;j++)
                        R[3*i+j] = U[i][0]*V[j][0] + U[i][1]*V[j][1] + U[i][2]*V[j][2];

                #pragma unroll
                for (int i=0;i<9;i++) invp[i] = __float2bfloat16(f[i]);
                #pragma unroll
                for (int i=0;i<3;i++)
                    #pragma unroll
                    for (int j=0;j<3;j++) invp[9 + 3*i + j] = __float2bfloat16(U[i][j]);
                #pragma unroll
                for (int i=0;i<3;i++) invp[18+i] = __float2bfloat16(sig[i]);
                #pragma unroll
                for (int i=0;i<3;i++)
                    #pragma unroll
                    for (int j=0;j<3;j++) invp[21 + 3*i + j] = __float2bfloat16(V[j][i]);
                #pragma unroll 8
                for (int c=0;c<64;c++) invp[30+c] = __float2bfloat16(latp[c]);
                invp[94] = __float2bfloat16(0.0f);
                invp[95] = __float2bfloat16(0.0f);

                #pragma unroll
                for (int i=0;i<9;i++) { Fsm[tid*9+i] = f[i]; Rsm[tid*9+i] = R[i]; }
            } else {
                for (int i=0;i<K1PAD;i++) invp[i] = __float2bfloat16(0.0f);
            }
        }
        __syncthreads();

        // Layers 1-4: barrier-free (in-place, warp-private rows)
        gemm_mma<6, true>(A0, W1s, bsm);
        gemm_mma<8, true>(A0, W2s, bsm + HID);
        gemm_mma<8, true>(A0, W3s, bsm + 2*HID);
        gemm_mma<8, true>(A0, W4s, bsm + 3*HID);
        __syncthreads();

        // Layer 5 + symmetrize + R*x + F epilogue (thread t -> row t)
        if (tid < ROWS) {
            int r = base + tid;
            if (r < n) {
                const __nv_bfloat16* h = A0 + tid*PB;
                const float* b5s = bsm + 4*HID;
                float x[9];
                #pragma unroll
                for (int j=0;j<9;j++) x[j] = b5s[j];
                #pragma unroll 4
                for (int k2=0;k2<HID/2;k2++) {
                    __nv_bfloat162 hv = *(const __nv_bfloat162*)(h + 2*k2);
                    float a0 = __bfloat162float(hv.x);
                    float a1 = __bfloat162float(hv.y);
                    const float* w0 = W5s + (2*k2)*9;
                    #pragma unroll
                    for (int j=0;j<9;j++) x[j] = fmaf(a0, w0[j], x[j]);
                    #pragma unroll
                    for (int j=0;j<9;j++) x[j] = fmaf(a1, w0[9+j], x[j]);
                }
                float xs[9];
                #pragma unroll
                for (int i=0;i<3;i++)
                    #pragma unroll
                    for (int j=0;j<3;j++)
                        xs[3*i+j] = 0.5f*(x[3*i+j] + x[3*j+i]);

                const float* R  = Rsm + tid*9;
                const float* Ff = Fsm + tid*9;
                float* op = out + (size_t)r*9;
                #pragma unroll
                for (int i=0;i<3;i++)
                    #pragma unroll
                    for (int j=0;j<3;j++)
                        op[3*i+j] = ALPHA_C*(R[3*i+0]*xs[0+j] + R[3*i+1]*xs[3+j] + R[3*i+2]*xs[6+j])
                                    + Ff[3*i+j];
            }
        }
        // no barrier needed: rows/F/R are thread-private between epilogue and next phase-1;
        // post-phase-1 barrier protects the GEMM reads.
    }
}

extern "C" void kernel_launch(void* const* d_in, const int* in_sizes, int n_in,
                              void* d_out, int out_size)
{
    const float* F    = (const float*)d_in[0];
    const float* latw = (const float*)d_in[1];
    const float* W1   = (const float*)d_in[2];
    const float* b1   = (const float*)d_in[3];
    const float* W2   = (const float*)d_in[4];
    const float* b2   = (const float*)d_in[5];
    const float* W3   = (const float*)d_in[6];
    const float* b3   = (const float*)d_in[7];
    const float* W4   = (const float*)d_in[8];
    const float* b4   = (const float*)d_in[9];
    const float* W5   = (const float*)d_in[10];
    const float* b5   = (const float*)d_in[11];
    const int*   traj = (const int*)d_in[12];
    float* out = (float*)d_out;

    int n = in_sizes[0] / 9;
    int ntiles = (n + ROWS - 1) / ROWS;

    int sms = 148;
    cudaDeviceGetAttribute(&sms, cudaDevAttrMultiProcessorCount, 0);
    int grid = sms < ntiles ? sms : ntiles;

    cudaFuncSetAttribute(fproj_kernel, cudaFuncAttributeMaxDynamicSharedMemorySize, SMEM_BYTES);
    fproj_kernel<<<grid, NTHREADS, SMEM_BYTES>>>(F, latw, W1,b1, W2,b2, W3,b3, W4,b4, W5,b5,
                                                 traj, out, n, ntiles);
}

// round 16
// speedup vs baseline: 1.0061x; 1.0027x over previous
#include <cuda_runtime.h>
#include <cuda_bf16.h>
#include <math.h>
#include <stdint.h>

#define HID       128
#define INDIM     94
#define K1PAD     96
#define ROWS      256      // rows per tile
#define NTHREADS  512      // 16 warps
#define PB        136      // bf16 smem pitch
#define ALPHA_C   0.1f

// ---------------- shared memory layout (bytes) ----------------
#define OFF_A0   0
#define OFF_W1   (OFF_A0 + ROWS*PB*2)        // 69632
#define OFF_W2   (OFF_W1 + K1PAD*PB*2)       // +26112
#define OFF_W3   (OFF_W2 + HID*PB*2)         // +34816
#define OFF_W4   (OFF_W3 + HID*PB*2)
#define OFF_W5   (OFF_W4 + HID*PB*2)         // fp32 128*9
#define OFF_BIAS (OFF_W5 + HID*9*4)          // b1..b4 (512) + b5 (9) + pad
#define OFF_F    (OFF_BIAS + (4*HID+16)*4)
#define OFF_R    (OFF_F + ROWS*9*4)
#define SMEM_BYTES (OFF_R + ROWS*9*4)        // 225344 <= 232448

// ---------------- SVD helpers ----------------
template<int P,int Q>
__device__ __forceinline__ void jrot(float S[3][3], float V[3][3]) {
    float apq = S[P][Q];
    if (fabsf(apq) > 1e-20f) {
        float theta = (S[Q][Q] - S[P][P]) / (2.0f * apq);
        float t = copysignf(1.0f, theta) / (fabsf(theta) + sqrtf(1.0f + theta*theta));
        float c = rsqrtf(1.0f + t*t);
        float s = t * c;
        #pragma unroll
        for (int k=0;k<3;k++){ float a=S[k][P], b=S[k][Q]; S[k][P]=c*a-s*b; S[k][Q]=s*a+c*b; }
        #pragma unroll
        for (int k=0;k<3;k++){ float a=S[P][k], b=S[Q][k]; S[P][k]=c*a-s*b; S[P][k]=c*a-s*b; S[P][k]=c*a-s*b; S[P][k]=c*a-s*b; S[P][k]=c*a-s*b; S[P][k]=c*a-s*b; S[P][k]=c*a-s*b; S[P][k]=c*a-s*b; }
    }
}
// NOTE: corrected clean version below (the above is wrong); real one used:
template<int P,int Q>
__device__ __forceinline__ void jrot2(float S[3][3], float V[3][3]) {
    float apq = S[P][Q];
    if (fabsf(apq) > 1e-20f) {
        float theta = (S[Q][Q] - S[P][P]) / (2.0f * apq);
        float t = copysignf(1.0f, theta) / (fabsf(theta) + sqrtf(1.0f + theta*theta));
        float c = rsqrtf(1.0f + t*t);
        float s = t * c;
        #pragma unroll
        for (int k=0;k<3;k++){ float a=S[k][P], b=S[k][Q]; S[k][P]=c*a-s*b; S[k][Q]=s*a+c*b; }
        #pragma unroll
        for (int k=0;k<3;k++){ float a=S[P][k], b=S[Q][k]; S[P][k]=c*a-s*b; S[Q][k]=s*a+c*b; }
        #pragma unroll
        for (int k=0;k<3;k++){ float a=V[k][P], b=V[k][Q]; V[k][P]=c*a-s*b; V[k][Q]=s*a+c*b; }
    }
}
template<int J>
__device__ __forceinline__ void signfix(float V[3][3]) {
    float a=V[0][J], b=V[1][J], c=V[2][J];
    float aa=fabsf(a), ab=fabsf(b), ac=fabsf(c);
    float key = (aa>=ab) ? ((aa>=ac)? a : c) : ((ab>=ac)? b : c);
    if (key < 0.0f){ V[0][J]=-a; V[1][J]=-b; V[2][J]=-c; }
}
template<int I,int J>
__device__ __forceinline__ void cswap(float* e, float V[3][3]) {
    if (e[I] < e[J]) {
        float t=e[I]; e[I]=e[J]; e[J]=t;
        #pragma unroll
        for (int k=0;k<3;k++){ float v=V[k][I]; V[k][I]=V[k][J]; V[k][J]=v; }
    }
}

__device__ __forceinline__ float gelu_f(float x) {
    float u = x * (0.7978845608f + 0.0356774081f * x * x);
    float th;
    asm("tanh.approx.f32 %0, %1;" : "=f"(th) : "f"(u));
    return 0.5f * x * (1.0f + th);
}

// stage fp32 [K][128] global -> bf16 smem [K][PB]
__device__ __forceinline__ void stage_w(const float* __restrict__ g, __nv_bfloat16* __restrict__ s,
                                        int K, int t, int nt) {
    int total = K * HID;
    for (int i = t*4; i < total; i += nt*4) {
        float4 v = *(const float4*)(g + i);
        int k = i >> 7, nn = i & 127;
        __nv_bfloat16* d = s + k*PB + nn;
        *(__nv_bfloat162*)(d)     = __floats2bfloat162_rn(v.x, v.y);
        *(__nv_bfloat162*)(d + 2) = __floats2bfloat162_rn(v.z, v.w);
    }
}

// In-place GEMM: A[256 x 16*KT] @ W[16*KT x 128] -> A[256 x 128], bf16 in/out, f32 acc.
// 16 warps; warp w owns rows 16w..16w+15. All A-frags preloaded -> in-place safe.
// No block barrier needed (each warp reads/writes only its own rows); __syncwarp at end.
template<int KT, bool ACT>
__device__ __forceinline__ void gemm_mma(__nv_bfloat16* __restrict__ A,
                                         const __nv_bfloat16* __restrict__ W,
                                         const float* __restrict__ bias)
{
    const int warp = threadIdx.x >> 5;
    const int lane = threadIdx.x & 31;

    uint32_t aAddr = (uint32_t)__cvta_generic_to_shared(
        A + (warp*16 + (lane & 15))*PB + ((lane >> 4) << 3));
    uint32_t wBase = (uint32_t)__cvta_generic_to_shared(W)
        + (uint32_t)(((lane & 15)*PB + ((lane >> 4) << 3)) * 2);

    // preload all A fragments (needed for in-place update)
    uint32_t af[KT][4];
    #pragma unroll
    for (int kb=0; kb<KT; kb++)
        asm volatile("ldmatrix.sync.aligned.m8n8.x4.shared.b16 {%0,%1,%2,%3},[%4];"
            : "=r"(af[kb][0]),"=r"(af[kb][1]),"=r"(af[kb][2]),"=r"(af[kb][3])
            : "r"(aAddr + kb*32));

    float acc[16][4];
    #pragma unroll
    for (int t=0;t<16;t++){ acc[t][0]=0.f; acc[t][1]=0.f; acc[t][2]=0.f; acc[t][3]=0.f; }

    #pragma unroll
    for (int tp=0; tp<8; tp++) {
        #pragma unroll
        for (int kb=0; kb<KT; kb++) {
            uint32_t b0,b1,b2,b3;
            asm volatile("ldmatrix.sync.aligned.m8n8.x4.trans.shared.b16 {%0,%1,%2,%3},[%4];"
                : "=r"(b0),"=r"(b1),"=r"(b2),"=r"(b3)
                : "r"(wBase + (uint32_t)((kb*16*PB + 16*tp)*2)));
            asm volatile("mma.sync.aligned.m16n8k16.row.col.f32.bf16.bf16.f32 "
                "{%0,%1,%2,%3},{%4,%5,%6,%7},{%8,%9},{%0,%1,%2,%3};"
                : "+f"(acc[2*tp][0]),"+f"(acc[2*tp][1]),"+f"(acc[2*tp][2]),"+f"(acc[2*tp][3])
                : "r"(af[kb][0]),"r"(af[kb][1]),"r"(af[kb][2]),"r"(af[kb][3]),"r"(b0),"r"(b1));
            asm volatile("mma.sync.aligned.m16n8k16.row.col.f32.bf16.bf16.f32 "
                "{%0,%1,%2,%3},{%4,%5,%6,%7},{%8,%9},{%0,%1,%2,%3};"
                : "+f"(acc[2*tp+1][0]),"+f"(acc[2*tp+1][1]),"+f"(acc[2*tp+1][2]),"+f"(acc[2*tp+1][3])
                : "r"(af[kb][0]),"r"(af[kb][1]),"r"(af[kb][2]),"r"(af[kb][3]),"r"(b2),"r"(b3));
        }
    }

    const int g  = lane >> 2;
    const int c4 = lane & 3;
    const int r0 = warp*16 + g;
    #pragma unroll
    for (int t=0;t<16;t++) {
        int col = t*8 + c4*2;
        float2 bb = *(const float2*)(bias + col);
        float v0 = acc[t][0] + bb.x;
        float v1 = acc[t][1] + bb.y;
        float v2 = acc[t][2] + bb.x;
        float v3 = acc[t][3] + bb.y;
        if (ACT) { v0 = gelu_f(v0); v1 = gelu_f(v1); v2 = gelu_f(v2); v3 = gelu_f(v3); }
        *(__nv_bfloat162*)(A + r0*PB + col)     = __floats2bfloat162_rn(v0, v1);
        *(__nv_bfloat162*)(A + (r0+8)*PB + col) = __floats2bfloat162_rn(v2, v3);
    }
    __syncwarp();
}

__global__ void __launch_bounds__(NTHREADS, 1)
fproj_kernel(const float* __restrict__ Fg,
             const float* __restrict__ latw,
             const float* __restrict__ W1, const float* __restrict__ b1,
             const float* __restrict__ W2, const float* __restrict__ b2,
             const float* __restrict__ W3, const float* __restrict__ b3,
             const float* __restrict__ W4, const float* __restrict__ b4,
             const float* __restrict__ W5, const float* __restrict__ b5,
             const int* __restrict__ traj,
             float* __restrict__ out, int n, int ntiles)
{
    extern __shared__ __align__(16) unsigned char smraw[];
    __nv_bfloat16* A0  = (__nv_bfloat16*)(smraw + OFF_A0);
    __nv_bfloat16* W1s = (__nv_bfloat16*)(smraw + OFF_W1);
    __nv_bfloat16* W2s = (__nv_bfloat16*)(smraw + OFF_W2);
    __nv_bfloat16* W3s = (__nv_bfloat16*)(smraw + OFF_W3);
    __nv_bfloat16* W4s = (__nv_bfloat16*)(smraw + OFF_W4);
    float*         W5s = (float*)(smraw + OFF_W5);
    float*         bsm = (float*)(smraw + OFF_BIAS);
    float*         Fsm = (float*)(smraw + OFF_F);
    float*         Rsm = (float*)(smraw + OFF_R);

    const int tid = threadIdx.x;

    // ---- one-time weight staging (all 512 threads) ----
    stage_w(W1, W1s, INDIM, tid, NTHREADS);
    for (int i = tid; i < 2*HID; i += NTHREADS) {            // zero-pad W1 rows 94,95
        int k = INDIM + (i >> 7), nn = i & 127;
        W1s[k*PB + nn] = __float2bfloat16(0.0f);
    }
    stage_w(W2, W2s, HID, tid, NTHREADS);
    stage_w(W3, W3s, HID, tid, NTHREADS);
    stage_w(W4, W4s, HID, tid, NTHREADS);
    for (int i = tid; i < HID*9; i += NTHREADS) W5s[i] = W5[i];
    if (tid < HID)      bsm[tid]       = b1[tid];
    else if (tid < 2*HID) bsm[tid]     = b2[tid-HID];
    else if (tid < 3*HID) bsm[tid]     = b3[tid-2*HID];
    else if (tid < 4*HID) bsm[tid]     = b4[tid-3*HID];
    if (tid < 9) bsm[4*HID + tid] = b5[tid];
    const float* latp = latw + (size_t)traj[0] * 64;
    __syncthreads();

    // ---- persistent tile loop ----
    for (int tile = blockIdx.x; tile < ntiles; tile += gridDim.x) {
        const int base = tile * ROWS;

        // Phase 1: threads 0-255 -> SVD + input assembly for row (base+tid)
        if (tid < ROWS) {
            int r = base + tid;
            __nv_bfloat16* invp = A0 + tid*PB;
            if (r < n) {
                const float* fp = Fg + (size_t)r*9;
                float f[9];
                #pragma unroll
                for (int i=0;i<9;i++) f[i] = fp[i];

                float S[3][3];
                #pragma unroll
                for (int i=0;i<3;i++)
                    #pragma unroll
                    for (int j=0;j<3;j++)
                        S[i][j] = f[0+i]*f[0+j] + f[3+i]*f[3+j] + f[6+i]*f[6+j];

                float V[3][3] = {{1,0,0},{0,1,0},{0,0,1}};
                #pragma unroll
                for (int sw=0; sw<6; sw++) { jrot2<0,1>(S,V); jrot2<0,2>(S,V); jrot2<1,2>(S,V); }

                float e[3] = {S[0][0], S[1][1], S[2][2]};
                cswap<0,1>(e,V); cswap<0,2>(e,V); cswap<1,2>(e,V);
                signfix<0>(V); signfix<1>(V); signfix<2>(V);

                float sig[3];
                #pragma unroll
                for (int j=0;j<3;j++) sig[j] = sqrtf(fmaxf(e[j], 0.0f));

                float U[3][3];
                #pragma unroll
                for (int j=0;j<3;j++) {
                    float inv_s = 1.0f / sig[j];
                    #pragma unroll
                    for (int i=0;i<3;i++)
                        U[i][j] = (f[3*i+0]*V[0][j] + f[3*i+1]*V[1][j] + f[3*i+2]*V[2][j]) * inv_s;
                }

                float R[9];
                #pragma unroll
                for (int i=0;i<3;i++)
                    #pragma unroll
                    for (int j=0;j<3;j++)
                        R[3*i+j] = U[i][0]*V[j][0] + U[i][1]*V[j][1] + U[i][2]*V[j][2];

                #pragma unroll
                for (int i=0;i<9;i++) invp[i] = __float2bfloat16(f[i]);
                #pragma unroll
                for (int i=0;i<3;i++)
                    #pragma unroll
                    for (int j=0;j<3;j++) invp[9 + 3*i + j] = __float2bfloat16(U[i][j]);
                #pragma unroll
                for (int i=0;i<3;i++) invp[18+i] = __float2bfloat16(sig[i]);
                #pragma unroll
                for (int i=0;i<3;i++)
                    #pragma unroll
                    for (int j=0;j<3;j++) invp[21 + 3*i + j] = __float2bfloat16(V[j][i]);
                #pragma unroll 8
                for (int c=0;c<64;c++) invp[30+c] = __float2bfloat16(latp[c]);
                invp[94] = __float2bfloat16(0.0f);
                invp[95] = __float2bfloat16(0.0f);

                #pragma unroll
                for (int i=0;i<9;i++) { Fsm[tid*9+i] = f[i]; Rsm[tid*9+i] = R[i]; }
            } else {
                for (int i=0;i<K1PAD;i++) invp[i] = __float2bfloat16(0.0f);
            }
        }
        __syncthreads();

        // Layers 1-4: barrier-free (in-place, warp-private rows)
        gemm_mma<6, true>(A0, W1s, bsm);
        gemm_mma<8, true>(A0, W2s, bsm + HID);
        gemm_mma<8, true>(A0, W3s, bsm + 2*HID);
        gemm_mma<8, true>(A0, W4s, bsm + 3*HID);
        __syncthreads();

        // Layer 5 + symmetrize + R*x + F epilogue (thread t -> row t)
        if (tid < ROWS) {
            int r = base + tid;
            if (r < n) {
                const __nv_bfloat16* h = A0 + tid*PB;
                const float* b5s = bsm + 4*HID;
                float x[9];
                #pragma unroll
                for (int j=0;j<9;j++) x[j] = b5s[j];
                #pragma unroll 4
                for (int k2=0;k2<HID/2;k2++) {
                    __nv_bfloat162 hv = *(const __nv_bfloat162*)(h + 2*k2);
                    float a0 = __bfloat162float(hv.x);
                    float a1 = __bfloat162float(hv.y);
                    const float* w0 = W5s + (2*k2)*9;
                    #pragma unroll
                    for (int j=0;j<9;j++) x[j] = fmaf(a0, w0[j], x[j]);
                    #pragma unroll
                    for (int j=0;j<9;j++) x[j] = fmaf(a1, w0[9+j], x[j]);
                }
                float xs[9];
                #pragma unroll
                for (int i=0;i<3;i++)
                    #pragma unroll
                    for (int j=0;j<3;j++)
                        xs[3*i+j] = 0.5f*(x[3*i+j] + x[3*j+i]);

                const float* R  = Rsm + tid*9;
                const float* Ff = Fsm + tid*9;
                float* op = out + (size_t)r*9;
                #pragma unroll
                for (int i=0;i<3;i++)
                    #pragma unroll
                    for (int j=0;j<3;j++)
                        op[3*i+j] = ALPHA_C*(R[3*i+0]*xs[0+j] + R[3*i+1]*xs[3+j] + R[3*i+2]*xs[6+j])
                                    + Ff[3*i+j];
            }
        }
        // no barrier needed: rows/F/R are thread-private between epilogue and next phase-1;
        // post-phase-1 barrier protects the GEMM reads.
    }
}

extern "C" void kernel_launch(void* const* d_in, const int* in_sizes, int n_in,
                              void* d_out, int out_size)
{
    const float* F    = (const float*)d_in[0];
    const float* latw = (const float*)d_in[1];
    const float* W1   = (const float*)d_in[2];
    const float* b1   = (const float*)d_in[3];
    const float* W2   = (const float*)d_in[4];
    const float* b2   = (const float*)d_in[5];
    const float* W3   = (const float*)d_in[6];
    const float* b3   = (const float*)d_in[7];
    const float* W4   = (const float*)d_in[8];
    const float* b4   = (const float*)d_in[9];
    const float* W5   = (const float*)d_in[10];
    const float* b5   = (const float*)d_in[11];
    const int*   traj = (const int*)d_in[12];
    float* out = (float*)d_out;

    int n = in_sizes[0] / 9;
    int ntiles = (n + ROWS - 1) / ROWS;

    int sms = 148;
    cudaDeviceGetAttribute(&sms, cudaDevAttrMultiProcessorCount, 0);
    int grid = sms < ntiles ? sms : ntiles;

    cudaFuncSetAttribute(fproj_kernel, cudaFuncAttributeMaxDynamicSharedMemorySize, SMEM_BYTES);
    fproj_kernel<<<grid, NTHREADS, SMEM_BYTES>>>(F, latw, W1,b1, W2,b2, W3,b3, W4,b4, W5,b5,
                                                 traj, out, n, ntiles);
}